// round 2
// baseline (speedup 1.0000x reference)
#include <cuda_runtime.h>

// SIR recurrence: n-1 = 2047 serial steps over a 4-float live state.
// Strategy:
//   - thread 0 of a single block runs the recurrence, staging rows in SMEM
//     (STS is issue-only ~2cyc vs STG.32 issue cost 5cyc).
//   - algebra refactored to a 3-FFMA critical chain:
//       c   = fma(A, s0*s2, B),  A = w3^2/1000, B = w3*b3 + b3
//       s0' = fma(K, s0, c),     K = 1 - w2^2 - w4^2
//       s2' = s2 - c ; s1' = fma(w2^2, s0, s1) ; s3' = fma(w4^2, s0, s3)
//   - whole block then copies SMEM -> GMEM with float4 (output 41KB).
//   - slot 4 of every row is 0: SMEM is pre-zeroed in parallel.

#define MAX_OUT_FLOATS 10240   // (2048-1)*5 = 10235, padded to /4

__global__ void __launch_bounds__(256, 1)
sir_kernel(const float* __restrict__ x,
           const float* __restrict__ w2p,
           const float* __restrict__ w3p,
           const float* __restrict__ b3p,
           const float* __restrict__ w4p,
           float* __restrict__ out,
           int n)
{
    __shared__ float buf[MAX_OUT_FLOATS];

    const int tid   = threadIdx.x;
    const int nthr  = blockDim.x;
    const int total = (n - 1) * 5;

    // Pre-zero SMEM in parallel (covers slot-4 zeros and the float4 pad tail).
    for (int i = tid; i < MAX_OUT_FLOATS; i += nthr)
        buf[i] = 0.0f;
    __syncthreads();

    if (tid == 0) {
        float s0 = x[0], s1 = x[1], s2 = x[2], s3 = x[3];
        const float w2 = *w2p, w3 = *w3p, b3 = *b3p, w4 = *w4p;

        const float w2sq = w2 * w2;
        const float w4sq = w4 * w4;
        const float K    = 1.0f - w2sq - w4sq;
        const float A    = w3 * w3 * 1.0e-3f;
        const float B    = fmaf(w3, b3, b3);

        float* p = buf;
        const int steps = n - 1;
        #pragma unroll 4
        for (int i = 0; i < steps; ++i) {
            const float m   = s0 * s2;               // chain dep 1
            const float c   = fmaf(A, m, B);         // chain dep 2
            const float ns0 = fmaf(K, s0, c);        // chain dep 3 (12-cyc floor)
            s1 = fmaf(w2sq, s0, s1);                 // off-chain
            s3 = fmaf(w4sq, s0, s3);                 // off-chain
            s2 = s2 - c;                             // off-chain (dep on c)
            s0 = ns0;
            p[0] = s0; p[1] = s1; p[2] = s2; p[3] = s3;   // STS, issue-only
            p += 5;
        }
    }
    __syncthreads();

    // Parallel SMEM -> GMEM copy, float4 main body + scalar tail.
    const int nvec = total >> 2;                 // 2558 float4s for n=2048
    const float4* src4 = reinterpret_cast<const float4*>(buf);
    float4*       dst4 = reinterpret_cast<float4*>(out);
    for (int i = tid; i < nvec; i += nthr)
        dst4[i] = src4[i];
    const int tail_base = nvec << 2;
    for (int i = tail_base + tid; i < total; i += nthr)
        out[i] = buf[i];
}

extern "C" void kernel_launch(void* const* d_in, const int* in_sizes, int n_in,
                              void* d_out, int out_size)
{
    const float* x  = (const float*)d_in[0];
    const float* w2 = (const float*)d_in[1];
    const float* w3 = (const float*)d_in[2];
    const float* b3 = (const float*)d_in[3];
    const float* w4 = (const float*)d_in[4];
    float* out = (float*)d_out;

    // n is host-derivable from the preallocated output: out_size = (n-1)*5.
    const int n = out_size / 5 + 1;

    sir_kernel<<<1, 256>>>(x, w2, w3, b3, w4, out, n);
}

// round 4
// speedup vs baseline: 1.0292x; 1.0292x over previous
#include <cuda_runtime.h>

// SIR recurrence, round 2.
// Serial loop now carries ONLY the true 2-variable recurrence (s0, s2),
// re-associated to the 12-cycle chain floor:
//     inner = fma(K, s0, B)      (issuable at iter start)
//     pre   = s2 - B             (issuable at iter start)
//     m     = s0 * s2
//     ns0   = fma( A, m, inner)  = K*s0 + (A*m + B)   -> ready T+10
//     ns2   = fma(-A, m, pre)    = s2  - (A*m + B)    -> ready T+12
// 5 FMA-pipe ops (10 cyc pipe) + 2 STS per iter, under the 12-cyc dep chain.
//
// s1 and s3 are pure prefix-accumulations of s0:
//     s1[i] = x1 + w2^2 * (x0 + sum_{j<i} s0[j])
//     s3[i] = x3 + w4^2 * (x0 + sum_{j<i} s0[j])
// reconstructed afterward by a 256-thread block scan, then a float4 copy
// of the staged rows to GMEM.

#define MAX_ROWS   2048
#define BUF_FLOATS 10240   // 5*2047 = 10235, padded for float4 copy

__global__ void __launch_bounds__(256, 1)
sir_kernel(const float* __restrict__ x,
           const float* __restrict__ w2p,
           const float* __restrict__ w3p,
           const float* __restrict__ b3p,
           const float* __restrict__ w4p,
           float* __restrict__ out,
           int n)
{
    __shared__ float buf[BUF_FLOATS];
    __shared__ float wsum[8];

    const int tid   = threadIdx.x;
    const int nthr  = blockDim.x;
    const int steps = n - 1;
    const int total = steps * 5;

    // Pre-zero SMEM (covers slot-4 zeros and the float4 pad tail).
    for (int i = tid; i < BUF_FLOATS; i += nthr)
        buf[i] = 0.0f;
    __syncthreads();

    // ---- Phase 1: serial recurrence on thread 0 (chain-bound) ----
    if (tid == 0) {
        float s0 = x[0], s2 = x[2];
        const float w2 = *w2p, w3 = *w3p, b3 = *b3p, w4 = *w4p;

        const float K    =  1.0f - w2 * w2 - w4 * w4;
        const float A    =  w3 * w3 * 1.0e-3f;
        const float negA = -A;
        const float B    =  fmaf(w3, b3, b3);

        float* p = buf;
        #pragma unroll 8
        for (int i = 0; i < steps; ++i) {
            const float m     = s0 * s2;            // chain: T+4..8
            const float inner = fmaf(K, s0, B);     // off-chain, early
            const float pre   = s2 - B;             // off-chain, early
            const float ns0   = fmaf(A,    m, inner);  // ready ~T+10
            const float ns2   = fmaf(negA, m, pre);    // ready ~T+12
            s0 = ns0;
            s2 = ns2;
            p[0] = s0;                              // STS, issue-only
            p[2] = s2;
            p += 5;
        }
    }
    __syncthreads();

    // ---- Phase 2: parallel reconstruction of s1/s3 via block scan ----
    {
        const float x0 = x[0], x1 = x[1], x3 = x[3];
        const float w2 = *w2p, w4 = *w4p;
        const float w2sq = w2 * w2;
        const float w4sq = w4 * w4;

        // Each thread owns 8 consecutive rows.
        const int base = tid * 8;
        float loc[8];           // inclusive local prefix of s0_out
        float run = 0.0f;
        #pragma unroll
        for (int k = 0; k < 8; ++k) {
            const int r = base + k;
            const float v = (r < steps) ? buf[5 * r] : 0.0f;
            run += v;
            loc[k] = run;
        }

        // Warp-inclusive scan of per-thread totals.
        const unsigned lane = tid & 31u;
        const unsigned wid  = tid >> 5;
        float scan = run;
        #pragma unroll
        for (int off = 1; off < 32; off <<= 1) {
            const float o = __shfl_up_sync(0xffffffffu, scan, off);
            if (lane >= off) scan += o;
        }
        if (lane == 31) wsum[wid] = scan;
        __syncthreads();

        float woff = 0.0f;
        #pragma unroll
        for (unsigned w = 0; w < 8; ++w)
            if (w < wid) woff += wsum[w];

        // Exclusive prefix (sum of all s0_out before this thread's rows).
        const float texcl = woff + (scan - run);

        #pragma unroll
        for (int k = 0; k < 8; ++k) {
            const int r = base + k;
            if (r < steps) {
                const float Qexc = texcl + (k ? loc[k - 1] : 0.0f);
                const float S = x0 + Qexc;   // x0 + sum_{j<r} s0_out[j]
                buf[5 * r + 1] = fmaf(w2sq, S, x1);
                buf[5 * r + 3] = fmaf(w4sq, S, x3);
            }
        }
    }
    __syncthreads();

    // ---- Phase 3: coalesced SMEM -> GMEM copy ----
    const int nvec = total >> 2;
    const float4* src4 = reinterpret_cast<const float4*>(buf);
    float4*       dst4 = reinterpret_cast<float4*>(out);
    for (int i = tid; i < nvec; i += nthr)
        dst4[i] = src4[i];
    for (int i = (nvec << 2) + tid; i < total; i += nthr)
        out[i] = buf[i];
}

extern "C" void kernel_launch(void* const* d_in, const int* in_sizes, int n_in,
                              void* d_out, int out_size)
{
    const float* x  = (const float*)d_in[0];
    const float* w2 = (const float*)d_in[1];
    const float* w3 = (const float*)d_in[2];
    const float* b3 = (const float*)d_in[3];
    const float* w4 = (const float*)d_in[4];
    float* out = (float*)d_out;

    const int n = out_size / 5 + 1;   // out_size = (n-1)*5

    sir_kernel<<<1, 256>>>(x, w2, w3, b3, w4, out, n);
}